// round 4
// baseline (speedup 1.0000x reference)
#include <cuda_runtime.h>
#include <cstdint>

// Problem constants (fixed by setup_inputs)
#define Bc    16
#define Nc    4096
#define Cc    64
#define OUTc  128
#define Sc    1024
#define Kc    32
#define FEATc 67          // C + 3
#define PPB   32          // points per block in pointwise conv
#define FPT   16          // FPS points per thread (256 threads)

// Scratch (static __device__ arrays — no allocations allowed)
__device__ int   g_fps_idx[Bc * Sc];
__device__ int   g_knn_idx[Bc * Sc * Kc];
__device__ float g_A[(size_t)Bc * Nc * OUTc];   // 33.5 MB precomputed per-point conv

// Strictly non-fused squared norm: (dx*dx + dy*dy) + dz*dz, each op rounded.
__device__ __forceinline__ float sq3_nofma(float dx, float dy, float dz) {
    return __fadd_rn(__fadd_rn(__fmul_rn(dx, dx), __fmul_rn(dy, dy)), __fmul_rn(dz, dz));
}

// ---- packed f32x2 helpers (sm_100+; per-lane .rn == scalar rounding) ----
__device__ __forceinline__ unsigned long long pack2(float lo, float hi) {
    unsigned long long r;
    asm("mov.b64 %0, {%1, %2};" : "=l"(r) : "f"(lo), "f"(hi));
    return r;
}
__device__ __forceinline__ void unpack2(unsigned long long v, float& lo, float& hi) {
    asm("mov.b64 {%0, %1}, %2;" : "=f"(lo), "=f"(hi) : "l"(v));
}
__device__ __forceinline__ unsigned long long add2(unsigned long long a, unsigned long long b) {
    unsigned long long r;
    asm("add.rn.f32x2 %0, %1, %2;" : "=l"(r) : "l"(a), "l"(b));
    return r;
}
__device__ __forceinline__ unsigned long long mul2(unsigned long long a, unsigned long long b) {
    unsigned long long r;
    asm("mul.rn.f32x2 %0, %1, %2;" : "=l"(r) : "l"(a), "l"(b));
    return r;
}

// ---------------------------------------------------------------------------
// Kernel 1: Farthest Point Sampling. One block per batch, 256 threads,
// 16 points/thread fully register-resident as 8 f32x2 pairs. Packed-fp32
// arithmetic (exact per-lane .rn, sub == add of pre-negated centroid).
// Centroid read from gmem (broadcast LDG, L1-resident). One barrier per
// iteration: warp argmax via REDUX+ballot, leader stores packed (dist||~idx)
// u64 to parity-double-buffered slots; all threads reduce the 8 slots locally.
// ---------------------------------------------------------------------------
__global__ __launch_bounds__(256) void fps_kernel(const float* __restrict__ xyz) {
    const int b    = blockIdx.x;
    const int tid  = threadIdx.x;
    const int lane = tid & 31;
    const int w    = tid >> 5;
    const float* base = xyz + (size_t)b * Nc * 3;

    __shared__ unsigned long long s_best[2][8];

    unsigned long long px2[FPT / 2], py2[FPT / 2], pz2[FPT / 2];
    float dist[FPT];
#pragma unroll
    for (int p = 0; p < FPT / 2; p++) {
        int g = tid * FPT + 2 * p;
        px2[p] = pack2(base[g * 3 + 0], base[g * 3 + 3]);
        py2[p] = pack2(base[g * 3 + 1], base[g * 3 + 4]);
        pz2[p] = pack2(base[g * 3 + 2], base[g * 3 + 5]);
        dist[2 * p] = 1e10f; dist[2 * p + 1] = 1e10f;
    }

    int far = 0;  // deterministic start at index 0 (matches reference)

    for (int it = 0; it < Sc; it++) {
        if (tid == 0) g_fps_idx[b * Sc + it] = far;   // record PRE-update farthest

        const float cx = __ldg(base + far * 3 + 0);
        const float cy = __ldg(base + far * 3 + 1);
        const float cz = __ldg(base + far * 3 + 2);
        const unsigned long long ncx = pack2(-cx, -cx);
        const unsigned long long ncy = pack2(-cy, -cy);
        const unsigned long long ncz = pack2(-cz, -cz);

#pragma unroll
        for (int p = 0; p < FPT / 2; p++) {
            unsigned long long dx = add2(px2[p], ncx);   // x - cx (exact)
            unsigned long long dy = add2(py2[p], ncy);
            unsigned long long dz = add2(pz2[p], ncz);
            unsigned long long s  = add2(add2(mul2(dx, dx), mul2(dy, dy)), mul2(dz, dz));
            float lo, hi; unpack2(s, lo, hi);
            dist[2 * p]     = fminf(dist[2 * p],     lo);
            dist[2 * p + 1] = fminf(dist[2 * p + 1], hi);
        }

        // Thread argmax, strict > keeps first (smallest local index).
        float bd = dist[0]; int bj = 0;
#pragma unroll
        for (int j = 1; j < FPT; j++)
            if (dist[j] > bd) { bd = dist[j]; bj = j; }

        // Warp argmax (dist >= 0: float order == uint bit order).
        unsigned bdu = __float_as_uint(bd);
        unsigned mx  = __reduce_max_sync(0xFFFFFFFFu, bdu);
        unsigned msk = __ballot_sync(0xFFFFFFFFu, bdu == mx);
        int src  = __ffs(msk) - 1;                    // lowest lane == smallest index
        int widx = __shfl_sync(0xFFFFFFFFu, tid * FPT + bj, src);
        if (lane == 0)
            s_best[it & 1][w] = ((unsigned long long)mx << 32)
                              | (unsigned)(0xFFFFFFFFu - (unsigned)widx);
        __syncthreads();
        // Writes of this parity recur only in it+2, after it+1's barrier: race-free.

        unsigned long long best = s_best[it & 1][0];
#pragma unroll
        for (int k = 1; k < 8; k++) {
            unsigned long long v = s_best[it & 1][k];
            best = (v > best) ? v : best;
        }
        far = (int)(0xFFFFFFFFu - (unsigned)best);
    }
}

// ---------------------------------------------------------------------------
// Kernel 2: kNN via exact radix-select (rank 32) on ordered fp32 distance bits.
// One 128-thread block per query; 32 keys/thread register-resident.
// 4 passes of 8-bit SMEM histograms find T = 32nd-smallest distance and
// `need` = how many to take among keys == T (tie-break: smallest indices,
// matching top_k stability). Output order irrelevant (set semantics:
// downstream is gather + max-pool, both order-invariant).
// ---------------------------------------------------------------------------
__global__ __launch_bounds__(128) void knn_kernel(const float* __restrict__ xyz,
                                                  float* __restrict__ newxyz) {
    const int q = blockIdx.x, b = q >> 10, tid = threadIdx.x;

    __shared__ unsigned hist[256];
    __shared__ float    s_q[3];
    __shared__ unsigned s_sel, s_need;
    __shared__ int      s_cnt, s_tcnt;
    __shared__ int      tlist[64];

    const float* base = xyz + (size_t)b * Nc * 3;

    if (tid == 0) {
        int fi = g_fps_idx[q];
        float qx = base[fi * 3 + 0], qy = base[fi * 3 + 1], qz = base[fi * 3 + 2];
        s_q[0] = qx; s_q[1] = qy; s_q[2] = qz;
        newxyz[q * 3 + 0] = qx; newxyz[q * 3 + 1] = qy; newxyz[q * 3 + 2] = qz;
    }
    __syncthreads();

    const float qx = s_q[0], qy = s_q[1], qz = s_q[2];
    const float qq = sq3_nofma(qx, qy, qz);        // sum(new_xyz**2)

    unsigned key[32];
#pragma unroll
    for (int j = 0; j < 32; j++) {
        int i = tid + 128 * j;                      // coalesced-ish (nL=3)
        float x = base[i * 3 + 0], y = base[i * 3 + 1], z = base[i * 3 + 2];
        float pp  = sq3_nofma(x, y, z);
        float dot = __fadd_rn(__fadd_rn(__fmul_rn(qx, x), __fmul_rn(qy, y)),
                              __fmul_rn(qz, z));
        float sq  = __fsub_rn(__fadd_rn(qq, pp), __fmul_rn(2.0f, dot));
        unsigned u = __float_as_uint(sq);
        key[j] = (u & 0x80000000u) ? ~u : (u | 0x80000000u);  // total order
    }

    unsigned prefix = 0u;   // selected high bits (masked), consistent across threads
    unsigned need   = 32u;  // remaining rank within the current bucket

#pragma unroll
    for (int pass = 0; pass < 4; pass++) {
        const int shift = 24 - 8 * pass;
        const unsigned mh = pass ? (0xFFFFFFFFu << (shift + 8)) : 0u;

        hist[tid] = 0u; hist[tid + 128] = 0u;
        __syncthreads();
#pragma unroll
        for (int j = 0; j < 32; j++)
            if ((key[j] & mh) == prefix)
                atomicAdd(&hist[(key[j] >> shift) & 0xFFu], 1u);
        __syncthreads();

        if (tid < 32) {
            unsigned tot = 0;
#pragma unroll
            for (int t = 0; t < 8; t++) tot += hist[tid * 8 + t];
            unsigned incl = tot;                   // inclusive scan over lanes
#pragma unroll
            for (int o = 1; o < 32; o <<= 1) {
                unsigned v = __shfl_up_sync(0xFFFFFFFFu, incl, o);
                if (tid >= o) incl += v;
            }
            unsigned exb  = incl - tot;            // exclusive prefix
            unsigned ball = __ballot_sync(0xFFFFFFFFu, exb < need);
            int L = 31 - __clz(ball);              // deepest lane with exb < need
            if (tid == L) {
                unsigned cum = exb;
#pragma unroll
                for (int t = 0; t < 8; t++) {
                    unsigned h = hist[tid * 8 + t];
                    if (cum + h >= need) { s_sel = (unsigned)(tid * 8 + t);
                                           s_need = need - cum; break; }
                    cum += h;
                }
            }
        }
        __syncthreads();
        prefix |= s_sel << shift;
        need    = s_need;
        // (s_sel/s_need rewritten only after 2 more barriers next pass — safe)
    }

    const unsigned T = prefix;                     // exact 32nd-smallest key
    if (tid == 0) { s_cnt = 0; s_tcnt = 0; }
    __syncthreads();

    int* outk = g_knn_idx + (size_t)q * Kc;
#pragma unroll
    for (int j = 0; j < 32; j++) {
        int i = tid + 128 * j;
        if (key[j] < T)       { int p = atomicAdd(&s_cnt, 1);  outk[p] = i; }
        else if (key[j] == T) { int t = atomicAdd(&s_tcnt, 1); if (t < 64) tlist[t] = i; }
    }
    __syncthreads();

    if (tid == 0) {                                // fill ties, smallest index first
        int basep = s_cnt;                         // == 32 - need by construction
        int m = s_tcnt < 64 ? s_tcnt : 64;
        for (unsigned r = 0; r < need; r++) {
            int best = 0x7FFFFFFF, bp = 0;
            for (int t = 0; t < m; t++) if (tlist[t] < best) { best = tlist[t]; bp = t; }
            outk[basep + r] = best;
            tlist[bp] = 0x7FFFFFFF;
        }
    }
}

// ---------------------------------------------------------------------------
// Kernel 3a: per-point conv A[b,n,o] = W_xyz . xyz + W_vox . vox  (67 FMA each).
// Factors out the 8x-redundant per-group compute: W.(p - c) = (W.p) - (W.c).
// Block = 128 threads (thread = out channel), 32 points per block.
// ---------------------------------------------------------------------------
__global__ __launch_bounds__(128) void pointwise_kernel(
    const float* __restrict__ xyz, const float* __restrict__ voxels,
    const float* __restrict__ conv_w) {

    const int tid = threadIdx.x;
    const int p0  = blockIdx.x * PPB;              // flat point id (b*Nc + n)

    __shared__ __align__(16) float sv[PPB * Cc];   // 8 KB voxel tile
    __shared__ __align__(16) float sp[PPB * 3];

    const float4* vsrc = (const float4*)(voxels + (size_t)p0 * Cc);
    float4* vdst = (float4*)sv;
#pragma unroll
    for (int j = 0; j < (PPB * Cc / 4) / 128; j++) vdst[tid + j * 128] = vsrc[tid + j * 128];
    if (tid < PPB * 3) sp[tid] = xyz[(size_t)p0 * 3 + tid];

    const float* wr = conv_w + tid * FEATc;
    float wx = wr[0], wy = wr[1], wz = wr[2];
    float wv[Cc];
#pragma unroll
    for (int c = 0; c < Cc; c++) wv[c] = wr[3 + c];
    __syncthreads();

    float* Adst = g_A + (size_t)p0 * OUTc + tid;
    for (int p = 0; p < PPB; p++) {
        float acc = fmaf(wz, sp[p * 3 + 2], fmaf(wy, sp[p * 3 + 1], wx * sp[p * 3 + 0]));
        const float4* f4 = (const float4*)(sv + p * Cc);
#pragma unroll
        for (int c4 = 0; c4 < Cc / 4; c4++) {
            float4 f = f4[c4];                     // broadcast, conflict-free
            acc = fmaf(f.x, wv[c4 * 4 + 0], acc);
            acc = fmaf(f.y, wv[c4 * 4 + 1], acc);
            acc = fmaf(f.z, wv[c4 * 4 + 2], acc);
            acc = fmaf(f.w, wv[c4 * 4 + 3], acc);
        }
        Adst[(size_t)p * OUTc] = acc;              // coalesced per warp
    }
}

// ---------------------------------------------------------------------------
// Kernel 3b: per query: max_k A[idx_k] - (W_xyz . new_xyz) + bias -> LayerNorm.
// Pure gather+max (no per-neighbor FMA); one block per (b,s), thread = channel.
// ---------------------------------------------------------------------------
__global__ __launch_bounds__(128) void group_kernel(
    const float* __restrict__ conv_w, const float* __restrict__ conv_b,
    const float* __restrict__ ln_g, const float* __restrict__ ln_b,
    const float* __restrict__ newxyz, float* __restrict__ out) {

    const int q = blockIdx.x, b = q >> 10, tid = threadIdx.x;

    __shared__ int   sidx[Kc];
    __shared__ float sred[5];

    if (tid < Kc) sidx[tid] = g_knn_idx[(size_t)q * Kc + tid];
    __syncthreads();

    const float nx = newxyz[q * 3 + 0], ny = newxyz[q * 3 + 1], nz = newxyz[q * 3 + 2];
    const float* wr = conv_w + tid * FEATc;
    const float cq = fmaf(wr[2], nz, fmaf(wr[1], ny, wr[0] * nx));

    const float* Ab = g_A + (size_t)b * Nc * OUTc + tid;
    float m = -3.4e38f;
#pragma unroll 8
    for (int k = 0; k < Kc; k++)
        m = fmaxf(m, Ab[(size_t)sidx[k] * OUTc]);  // 512B/neighbor coalesced gathers

    const float val = m - cq + conv_b[tid];        // bias commutes with max

    // LayerNorm over 128 channels (1 value/thread)
    float v = val;
#pragma unroll
    for (int o = 16; o > 0; o >>= 1) v += __shfl_down_sync(0xFFFFFFFFu, v, o);
    if ((tid & 31) == 0) sred[tid >> 5] = v;
    __syncthreads();
    if (tid == 0) sred[4] = (sred[0] + sred[1]) + (sred[2] + sred[3]);
    __syncthreads();
    const float mu = sred[4] * (1.0f / (float)OUTc);

    const float d = val - mu;
    float v2 = d * d;
#pragma unroll
    for (int o = 16; o > 0; o >>= 1) v2 += __shfl_down_sync(0xFFFFFFFFu, v2, o);
    if ((tid & 31) == 0) sred[tid >> 5] = v2;
    __syncthreads();
    if (tid == 0) sred[4] = (sred[0] + sred[1]) + (sred[2] + sred[3]);
    __syncthreads();
    const float var = sred[4] * (1.0f / (float)OUTc);
    const float rs  = rsqrtf(var + 1e-5f);

    out[(size_t)q * OUTc + tid] = d * rs * ln_g[tid] + ln_b[tid];
}

// ---------------------------------------------------------------------------
extern "C" void kernel_launch(void* const* d_in, const int* in_sizes, int n_in,
                              void* d_out, int out_size) {
    const float* xyz    = (const float*)d_in[0];
    const float* voxels = (const float*)d_in[1];
    const float* conv_w = (const float*)d_in[2];
    const float* conv_b = (const float*)d_in[3];
    const float* ln_g   = (const float*)d_in[4];
    const float* ln_b   = (const float*)d_in[5];

    float* out    = (float*)d_out;                 // [B,S,OUT]
    float* newxyz = out + (size_t)Bc * Sc * OUTc;  // [B,S,3] appended (tuple order)

    fps_kernel      <<<Bc,            256>>>(xyz);
    pointwise_kernel<<<Bc * Nc / PPB, 128>>>(xyz, voxels, conv_w);
    knn_kernel      <<<Bc * Sc,       128>>>(xyz, newxyz);
    group_kernel    <<<Bc * Sc,       128>>>(conv_w, conv_b, ln_g, ln_b, newxyz, out);
}

// round 8
// speedup vs baseline: 1.3684x; 1.3684x over previous
#include <cuda_runtime.h>
#include <cstdint>

// Problem constants (fixed by setup_inputs)
#define Bc    16
#define Nc    4096
#define Cc    64
#define OUTc  128
#define Sc    1024
#define Kc    32
#define FEATc 67          // C + 3
#define FPT   16          // FPS points per thread (256 threads)
#define PWP   64          // points per pointwise block (256 threads)

// Scratch (static __device__ arrays — no allocations allowed)
__device__ int   g_fps_idx[Bc * Sc];
__device__ float g_A[(size_t)Bc * Nc * OUTc];   // 33.5 MB precomputed per-point conv

// Strictly non-fused squared norm: (dx*dx + dy*dy) + dz*dz, each op rounded.
__device__ __forceinline__ float sq3_nofma(float dx, float dy, float dz) {
    return __fadd_rn(__fadd_rn(__fmul_rn(dx, dx), __fmul_rn(dy, dy)), __fmul_rn(dz, dz));
}

// ---- packed f32x2 helpers (sm_100+; per-lane .rn == scalar rounding) ----
__device__ __forceinline__ unsigned long long pack2(float lo, float hi) {
    unsigned long long r;
    asm("mov.b64 %0, {%1, %2};" : "=l"(r) : "f"(lo), "f"(hi));
    return r;
}
__device__ __forceinline__ void unpack2(unsigned long long v, float& lo, float& hi) {
    asm("mov.b64 {%0, %1}, %2;" : "=f"(lo), "=f"(hi) : "l"(v));
}
__device__ __forceinline__ unsigned long long add2(unsigned long long a, unsigned long long b) {
    unsigned long long r;
    asm("add.rn.f32x2 %0, %1, %2;" : "=l"(r) : "l"(a), "l"(b));
    return r;
}
__device__ __forceinline__ unsigned long long mul2(unsigned long long a, unsigned long long b) {
    unsigned long long r;
    asm("mul.rn.f32x2 %0, %1, %2;" : "=l"(r) : "l"(a), "l"(b));
    return r;
}

// ---------------------------------------------------------------------------
// Kernel 1 (fused): blocks 0..15 run FPS (one per batch, latency-bound on 16
// SMs); remaining 1024 blocks run the per-point conv A = W_xyz.xyz + W_vox.vox,
// which executes concurrently on the otherwise-idle SMs (hidden under FPS).
// ---------------------------------------------------------------------------
__global__ __launch_bounds__(256) void fps_pointwise_kernel(
    const float* __restrict__ xyz, const float* __restrict__ voxels,
    const float* __restrict__ conv_w) {

    __shared__ unsigned long long s_best[2][8];        // FPS branch
    __shared__ __align__(16) float sv[PWP * Cc];       // pointwise branch (16 KB)
    __shared__ __align__(16) float sp[PWP * 3];

    const int tid = threadIdx.x;

    if (blockIdx.x < Bc) {
        // ---------------- FPS: 256 threads, 16 pts/thread in f32x2 regs -----
        const int b    = blockIdx.x;
        const int lane = tid & 31;
        const int w    = tid >> 5;
        const float* base = xyz + (size_t)b * Nc * 3;

        unsigned long long px2[FPT / 2], py2[FPT / 2], pz2[FPT / 2];
        float dist[FPT];
#pragma unroll
        for (int p = 0; p < FPT / 2; p++) {
            int g = tid * FPT + 2 * p;
            px2[p] = pack2(base[g * 3 + 0], base[g * 3 + 3]);
            py2[p] = pack2(base[g * 3 + 1], base[g * 3 + 4]);
            pz2[p] = pack2(base[g * 3 + 2], base[g * 3 + 5]);
            dist[2 * p] = 1e10f; dist[2 * p + 1] = 1e10f;
        }

        int far = 0;  // deterministic start at index 0 (matches reference)

        for (int it = 0; it < Sc; it++) {
            if (tid == 0) g_fps_idx[b * Sc + it] = far;   // PRE-update farthest

            const float cx = __ldg(base + far * 3 + 0);
            const float cy = __ldg(base + far * 3 + 1);
            const float cz = __ldg(base + far * 3 + 2);
            const unsigned long long ncx = pack2(-cx, -cx);
            const unsigned long long ncy = pack2(-cy, -cy);
            const unsigned long long ncz = pack2(-cz, -cz);

#pragma unroll
            for (int p = 0; p < FPT / 2; p++) {
                unsigned long long dx = add2(px2[p], ncx);   // x - cx (exact)
                unsigned long long dy = add2(py2[p], ncy);
                unsigned long long dz = add2(pz2[p], ncz);
                unsigned long long s  = add2(add2(mul2(dx, dx), mul2(dy, dy)),
                                             mul2(dz, dz));
                float lo, hi; unpack2(s, lo, hi);
                dist[2 * p]     = fminf(dist[2 * p],     lo);
                dist[2 * p + 1] = fminf(dist[2 * p + 1], hi);
            }

            // Thread argmax, strict > keeps first (smallest local index).
            float bd = dist[0]; int bj = 0;
#pragma unroll
            for (int j = 1; j < FPT; j++)
                if (dist[j] > bd) { bd = dist[j]; bj = j; }

            // Warp argmax (dist >= 0: float order == uint bit order).
            unsigned bdu = __float_as_uint(bd);
            unsigned mx  = __reduce_max_sync(0xFFFFFFFFu, bdu);
            unsigned msk = __ballot_sync(0xFFFFFFFFu, bdu == mx);
            int src  = __ffs(msk) - 1;                 // lowest lane = smallest idx
            int widx = __shfl_sync(0xFFFFFFFFu, tid * FPT + bj, src);
            if (lane == 0)
                s_best[it & 1][w] = ((unsigned long long)mx << 32)
                                  | (unsigned)(0xFFFFFFFFu - (unsigned)widx);
            __syncthreads();
            // Same-parity rewrite only at it+2, after it+1's barrier: race-free.

            unsigned long long best = s_best[it & 1][0];
#pragma unroll
            for (int k = 1; k < 8; k++) {
                unsigned long long v = s_best[it & 1][k];
                best = (v > best) ? v : best;
            }
            far = (int)(0xFFFFFFFFu - (unsigned)best);
        }
    } else {
        // ---------------- pointwise conv: 64 points, thread = (half, channel)
        const int ch   = tid & 127;
        const int half = tid >> 7;
        const int p0   = (blockIdx.x - Bc) * PWP;      // flat point id

        const float4* vsrc = (const float4*)(voxels + (size_t)p0 * Cc);
        float4* vdst = (float4*)sv;
#pragma unroll
        for (int j = 0; j < (PWP * Cc / 4) / 256; j++)
            vdst[tid + j * 256] = vsrc[tid + j * 256];
        if (tid < PWP * 3) sp[tid] = xyz[(size_t)p0 * 3 + tid];

        const float* wr = conv_w + ch * FEATc;
        float wx = wr[0], wy = wr[1], wz = wr[2];
        float wv[Cc];
#pragma unroll
        for (int c = 0; c < Cc; c++) wv[c] = wr[3 + c];
        __syncthreads();

        const int pbeg = half * (PWP / 2);
        float* Adst = g_A + (size_t)(p0 + pbeg) * OUTc + ch;
        for (int p = 0; p < PWP / 2; p++) {
            const float* srow = sp + (pbeg + p) * 3;
            float acc = fmaf(wz, srow[2], fmaf(wy, srow[1], wx * srow[0]));
            const float4* f4 = (const float4*)(sv + (pbeg + p) * Cc);
#pragma unroll
            for (int c4 = 0; c4 < Cc / 4; c4++) {
                float4 f = f4[c4];                     // broadcast, conflict-free
                acc = fmaf(f.x, wv[c4 * 4 + 0], acc);
                acc = fmaf(f.y, wv[c4 * 4 + 1], acc);
                acc = fmaf(f.z, wv[c4 * 4 + 2], acc);
                acc = fmaf(f.w, wv[c4 * 4 + 3], acc);
            }
            Adst[(size_t)p * OUTc] = acc;              // coalesced per warp
        }
    }
}

// ---------------------------------------------------------------------------
// Kernel 2 (fused): kNN radix-select (rank 32, exact, top_k-stable ties) with
// MATCH-AGGREGATED histogram atomics (distances cluster into ~5 hot bins ->
// naive per-lane atomics serialize ~32-way at 32 cyc/warp-instr; match_any
// makes ONE spread-address atomic per distinct bin per warp; in passes 1-3 a
// 2-cyc ballot skips the match when no lane is active), then the group stage
// (gather A + max + bias + LayerNorm) runs in the same block on the
// smem-resident index list.
// ---------------------------------------------------------------------------
__global__ __launch_bounds__(128) void knn_group_kernel(
    const float* __restrict__ xyz,
    const float* __restrict__ conv_w, const float* __restrict__ conv_b,
    const float* __restrict__ ln_g, const float* __restrict__ ln_b,
    float* __restrict__ newxyz, float* __restrict__ out) {

    const int q = blockIdx.x, b = q >> 10, tid = threadIdx.x, lane = tid & 31;

    __shared__ unsigned hist[256];
    __shared__ float    s_q[3];
    __shared__ unsigned s_sel, s_need;
    __shared__ int      s_cnt, s_tcnt;
    __shared__ int      tlist[64];
    __shared__ int      sidx[Kc];
    __shared__ float    sred[5];

    const float* base = xyz + (size_t)b * Nc * 3;

    if (tid == 0) {
        int fi = g_fps_idx[q];
        float qx = base[fi * 3 + 0], qy = base[fi * 3 + 1], qz = base[fi * 3 + 2];
        s_q[0] = qx; s_q[1] = qy; s_q[2] = qz;
        newxyz[q * 3 + 0] = qx; newxyz[q * 3 + 1] = qy; newxyz[q * 3 + 2] = qz;
    }
    __syncthreads();

    const float qx = s_q[0], qy = s_q[1], qz = s_q[2];
    const float qq = sq3_nofma(qx, qy, qz);        // sum(new_xyz**2)

    unsigned key[32];
#pragma unroll
    for (int j = 0; j < 32; j++) {
        int i = tid + 128 * j;                      // coalesced-ish
        float x = base[i * 3 + 0], y = base[i * 3 + 1], z = base[i * 3 + 2];
        float pp  = sq3_nofma(x, y, z);
        float dot = __fadd_rn(__fadd_rn(__fmul_rn(qx, x), __fmul_rn(qy, y)),
                              __fmul_rn(qz, z));
        float sq  = __fsub_rn(__fadd_rn(qq, pp), __fmul_rn(2.0f, dot));
        unsigned u = __float_as_uint(sq);
        key[j] = (u & 0x80000000u) ? ~u : (u | 0x80000000u);  // total order
    }

    unsigned prefix = 0u;   // selected high bits (masked), uniform across threads
    unsigned need   = 32u;  // remaining rank within the current bucket

#pragma unroll
    for (int pass = 0; pass < 4; pass++) {
        const int shift = 24 - 8 * pass;
        const unsigned mh = pass ? (0xFFFFFFFFu << (shift + 8)) : 0u;

        hist[tid] = 0u; hist[tid + 128] = 0u;
        __syncthreads();
#pragma unroll
        for (int j = 0; j < 32; j++) {
            bool act = ((key[j] & mh) == prefix);
            // Passes 1-3: usually no lane matches the prefix; ballot (2 cyc)
            // skips the multi-cycle match_any + atomic entirely.
            if (__ballot_sync(0xFFFFFFFFu, act)) {
                unsigned bin = act ? ((key[j] >> shift) & 0xFFu) : 0x1FFu;
                unsigned mm  = __match_any_sync(0xFFFFFFFFu, bin);
                if (act && lane == __ffs(mm) - 1)
                    atomicAdd(&hist[bin], (unsigned)__popc(mm)); // 1 atomic/bin/warp
            }
        }
        __syncthreads();

        if (tid < 32) {
            unsigned tot = 0;
#pragma unroll
            for (int t = 0; t < 8; t++) tot += hist[tid * 8 + t];
            unsigned incl = tot;                   // inclusive scan over lanes
#pragma unroll
            for (int o = 1; o < 32; o <<= 1) {
                unsigned v = __shfl_up_sync(0xFFFFFFFFu, incl, o);
                if (tid >= o) incl += v;
            }
            unsigned exb  = incl - tot;            // exclusive prefix
            unsigned ball = __ballot_sync(0xFFFFFFFFu, exb < need);
            int L = 31 - __clz(ball);              // deepest lane with exb < need
            if (tid == L) {
                unsigned cum = exb;
#pragma unroll
                for (int t = 0; t < 8; t++) {
                    unsigned h = hist[tid * 8 + t];
                    if (cum + h >= need) { s_sel = (unsigned)(tid * 8 + t);
                                           s_need = need - cum; break; }
                    cum += h;
                }
            }
        }
        __syncthreads();
        prefix |= s_sel << shift;
        need    = s_need;
        // (s_sel/s_need rewritten only after 2 more barriers next pass — safe)
    }

    const unsigned T = prefix;                     // exact 32nd-smallest key
    if (tid == 0) { s_cnt = 0; s_tcnt = 0; }
    __syncthreads();

#pragma unroll
    for (int j = 0; j < 32; j++) {
        int i = tid + 128 * j;
        if (key[j] < T)       { int p = atomicAdd(&s_cnt, 1);  sidx[p] = i; }
        else if (key[j] == T) { int t = atomicAdd(&s_tcnt, 1); if (t < 64) tlist[t] = i; }
    }
    __syncthreads();

    if (tid == 0) {                                // fill ties, smallest index first
        int basep = s_cnt;                         // == 32 - need by construction
        int m = s_tcnt < 64 ? s_tcnt : 64;
        for (unsigned r = 0; r < need; r++) {
            int best = 0x7FFFFFFF, bp = 0;
            for (int t = 0; t < m; t++) if (tlist[t] < best) { best = tlist[t]; bp = t; }
            sidx[basep + r] = best;
            tlist[bp] = 0x7FFFFFFF;
        }
    }
    __syncthreads();

    // ---------------- group stage: gather A + max + bias -> LayerNorm --------
    const float* wr = conv_w + tid * FEATc;
    const float cq = fmaf(wr[2], qz, fmaf(wr[1], qy, wr[0] * qx));

    const float* Ab = g_A + (size_t)b * Nc * OUTc + tid;
    float m = -3.4e38f;
#pragma unroll 8
    for (int k = 0; k < Kc; k++)
        m = fmaxf(m, Ab[(size_t)sidx[k] * OUTc]);  // 512B/neighbor coalesced gathers

    const float val = m - cq + conv_b[tid];        // bias commutes with max

    float v = val;
#pragma unroll
    for (int o = 16; o > 0; o >>= 1) v += __shfl_down_sync(0xFFFFFFFFu, v, o);
    if (lane == 0) sred[tid >> 5] = v;
    __syncthreads();
    if (tid == 0) sred[4] = (sred[0] + sred[1]) + (sred[2] + sred[3]);
    __syncthreads();
    const float mu = sred[4] * (1.0f / (float)OUTc);

    const float d = val - mu;
    float v2 = d * d;
#pragma unroll
    for (int o = 16; o > 0; o >>= 1) v2 += __shfl_down_sync(0xFFFFFFFFu, v2, o);
    if (lane == 0) sred[tid >> 5] = v2;
    __syncthreads();
    if (tid == 0) sred[4] = (sred[0] + sred[1]) + (sred[2] + sred[3]);
    __syncthreads();
    const float var = sred[4] * (1.0f / (float)OUTc);
    const float rs  = rsqrtf(var + 1e-5f);

    out[(size_t)q * OUTc + tid] = d * rs * ln_g[tid] + ln_b[tid];
}

// ---------------------------------------------------------------------------
extern "C" void kernel_launch(void* const* d_in, const int* in_sizes, int n_in,
                              void* d_out, int out_size) {
    const float* xyz    = (const float*)d_in[0];
    const float* voxels = (const float*)d_in[1];
    const float* conv_w = (const float*)d_in[2];
    const float* conv_b = (const float*)d_in[3];
    const float* ln_g   = (const float*)d_in[4];
    const float* ln_b   = (const float*)d_in[5];

    float* out    = (float*)d_out;                 // [B,S,OUT]
    float* newxyz = out + (size_t)Bc * Sc * OUTc;  // [B,S,3] appended (tuple order)

    fps_pointwise_kernel<<<Bc + Bc * Nc / PWP, 256>>>(xyz, voxels, conv_w);
    knn_group_kernel    <<<Bc * Sc,            128>>>(xyz, conv_w, conv_b,
                                                      ln_g, ln_b, newxyz, out);
}